// round 1
// baseline (speedup 1.0000x reference)
#include <cuda_runtime.h>
#include <math.h>

#define B_DIM 16
#define N_DIM 196608
#define BPB   128      // reduce blocks per batch
#define TPB   256
#define NACC  27       // 21 sym H entries + 6 g entries

// Fixed-slot partials: [value 0..26][batch 0..15][block 0..127]
__device__ float g_part[NACC * B_DIM * BPB];
// Unclipped delta_pose per batch (used by depth pass)
__device__ float g_dp[B_DIM * 6];

// ---------------------------------------------------------------------------
// Kernel 1: streaming per-point fused reduction -> 27 partials per block
// ---------------------------------------------------------------------------
__global__ void __launch_bounds__(TPB) reduce_kernel(
    const float* __restrict__ r, const float* __restrict__ w,
    const float* __restrict__ Jp, const float* __restrict__ Jd,
    const float* __restrict__ lmbda)
{
    const int b   = blockIdx.y;
    const int blk = blockIdx.x;
    const float lam = __ldg(lmbda + b);

    float acc[NACC];
#pragma unroll
    for (int i = 0; i < NACC; i++) acc[i] = 0.f;

    const size_t base = (size_t)b * N_DIM;

    for (int n = blk * TPB + threadIdx.x; n < N_DIM; n += BPB * TPB) {
        const size_t p = base + (size_t)n;
        const float2 rv = *(const float2*)(r  + 2 * p);
        const float2 wv = *(const float2*)(w  + 2 * p);
        const float2 jd = *(const float2*)(Jd + 2 * p);
        const float4 a0 = *(const float4*)(Jp + 12 * p);
        const float4 a1 = *(const float4*)(Jp + 12 * p + 4);
        const float4 a2 = *(const float4*)(Jp + 12 * p + 8);
        const float jp0[6] = {a0.x, a0.y, a0.z, a0.w, a1.x, a1.y};
        const float jp1[6] = {a1.z, a1.w, a2.x, a2.y, a2.z, a2.w};

        const float conf = wv.x;
        const float nl   = wv.y;

        float hpd[6];
#pragma unroll
        for (int i = 0; i < 6; i++)
            hpd[i] = conf * fmaf(jd.x, jp0[i], jd.y * jp1[i]);

        const float hdd = conf * fmaf(jd.x, jd.x, jd.y * jd.y);
        const float gd  = conf * fmaf(jd.x, rv.x, jd.y * rv.y);
        const float inv = 1.0f / fmaxf(hdd + lam + nl, 1e-4f);

        float cjp0[6], cjp1[6], ih[6];
#pragma unroll
        for (int i = 0; i < 6; i++) {
            cjp0[i] = conf * jp0[i];
            cjp1[i] = conf * jp1[i];
            ih[i]   = inv * hpd[i];
        }

        int idx = 0;
#pragma unroll
        for (int i = 0; i < 6; i++) {
#pragma unroll
            for (int j = i; j < 6; j++) {
                float t = acc[idx];
                t = fmaf(cjp0[i], jp0[j], t);
                t = fmaf(cjp1[i], jp1[j], t);
                t = fmaf(-ih[i], hpd[j], t);
                acc[idx++] = t;
            }
        }
#pragma unroll
        for (int i = 0; i < 6; i++) {
            float t = acc[21 + i];
            t = fmaf(cjp0[i], rv.x, t);
            t = fmaf(cjp1[i], rv.y, t);
            t = fmaf(-ih[i], gd, t);
            acc[21 + i] = t;
        }
    }

    // intra-warp tree reduce
#pragma unroll
    for (int off = 16; off; off >>= 1) {
#pragma unroll
        for (int i = 0; i < NACC; i++)
            acc[i] += __shfl_down_sync(0xFFFFFFFFu, acc[i], off);
    }

    __shared__ float sh[TPB / 32][NACC];
    const int wid  = threadIdx.x >> 5;
    const int lane = threadIdx.x & 31;
    if (lane == 0) {
#pragma unroll
        for (int i = 0; i < NACC; i++) sh[wid][i] = acc[i];
    }
    __syncthreads();

    if (threadIdx.x < NACC) {
        float s = 0.f;
#pragma unroll
        for (int wgi = 0; wgi < TPB / 32; wgi++) s += sh[wgi][threadIdx.x];
        g_part[threadIdx.x * (B_DIM * BPB) + b * BPB + blk] = s;
    }
}

// ---------------------------------------------------------------------------
// Kernel 2: final reduce + 6x6 damped solve per batch; write clipped pose out
// ---------------------------------------------------------------------------
__global__ void solve_kernel(const float* __restrict__ lmbda,
                             float* __restrict__ out_pose)
{
    const int b = blockIdx.x;
    const int t = threadIdx.x;
    __shared__ float sums[NACC];

    if (t < NACC) {
        const float* p = g_part + t * (B_DIM * BPB) + b * BPB;
        float s = 0.f;
#pragma unroll 8
        for (int i = 0; i < BPB; i++) s += p[i];
        sums[t] = s;
    }
    __syncthreads();

    if (t == 0) {
        double M[6][6], gv[6], x[6];
        int idx = 0;
        for (int i = 0; i < 6; i++)
            for (int j = i; j < 6; j++) {
                double v = (double)sums[idx++];
                M[i][j] = v; M[j][i] = v;
            }
        const double dd = (double)lmbda[b] + 0.011;
        for (int i = 0; i < 6; i++) M[i][i] += dd;
        for (int i = 0; i < 6; i++) gv[i] = (double)sums[21 + i];

        // LU with partial pivoting
        for (int c = 0; c < 6; c++) {
            int piv = c; double mx = fabs(M[c][c]);
            for (int rr = c + 1; rr < 6; rr++) {
                double a = fabs(M[rr][c]);
                if (a > mx) { mx = a; piv = rr; }
            }
            if (piv != c) {
                for (int j = 0; j < 6; j++) {
                    double tmp = M[c][j]; M[c][j] = M[piv][j]; M[piv][j] = tmp;
                }
                double tmp = gv[c]; gv[c] = gv[piv]; gv[piv] = tmp;
            }
            double d = M[c][c];
            if (d == 0.0) d = 1e-30;
            const double invd = 1.0 / d;
            for (int rr = c + 1; rr < 6; rr++) {
                const double f = M[rr][c] * invd;
                for (int j = c; j < 6; j++) M[rr][j] -= f * M[c][j];
                gv[rr] -= f * gv[c];
            }
        }
        for (int i = 5; i >= 0; i--) {
            double s = gv[i];
            for (int j = i + 1; j < 6; j++) s -= M[i][j] * x[j];
            x[i] = s / M[i][i];
        }

        for (int i = 0; i < 6; i++) {
            const float xf = (float)x[i];
            g_dp[b * 6 + i] = xf;                                  // unclipped
            out_pose[b * 6 + i] = fminf(fmaxf(xf, -2.0f), 2.0f);   // clipped
        }
    }
}

// ---------------------------------------------------------------------------
// Kernel 3: per-point depth: inv * (g_d - hpd . dp)   (dp UNclipped)
// ---------------------------------------------------------------------------
__global__ void __launch_bounds__(TPB) depth_kernel(
    const float* __restrict__ r, const float* __restrict__ w,
    const float* __restrict__ Jp, const float* __restrict__ Jd,
    const float* __restrict__ lmbda, float* __restrict__ out_depth)
{
    const int b = blockIdx.y;
    const int n = blockIdx.x * TPB + threadIdx.x;
    if (n >= N_DIM) return;

    const size_t p = (size_t)b * N_DIM + (size_t)n;
    const float lam = __ldg(lmbda + b);

    float dp[6];
#pragma unroll
    for (int i = 0; i < 6; i++) dp[i] = __ldg(g_dp + b * 6 + i);

    const float2 rv = *(const float2*)(r  + 2 * p);
    const float2 wv = *(const float2*)(w  + 2 * p);
    const float2 jd = *(const float2*)(Jd + 2 * p);
    const float4 a0 = *(const float4*)(Jp + 12 * p);
    const float4 a1 = *(const float4*)(Jp + 12 * p + 4);
    const float4 a2 = *(const float4*)(Jp + 12 * p + 8);

    const float conf = wv.x;
    const float nl   = wv.y;

    const float hdd = conf * fmaf(jd.x, jd.x, jd.y * jd.y);
    const float gd  = conf * fmaf(jd.x, rv.x, jd.y * rv.y);
    const float inv = 1.0f / fmaxf(hdd + lam + nl, 1e-4f);

    // jp0 . dp  and  jp1 . dp
    float dot0 = a0.x * dp[0];
    dot0 = fmaf(a0.y, dp[1], dot0);
    dot0 = fmaf(a0.z, dp[2], dot0);
    dot0 = fmaf(a0.w, dp[3], dot0);
    dot0 = fmaf(a1.x, dp[4], dot0);
    dot0 = fmaf(a1.y, dp[5], dot0);

    float dot1 = a1.z * dp[0];
    dot1 = fmaf(a1.w, dp[1], dot1);
    dot1 = fmaf(a2.x, dp[2], dot1);
    dot1 = fmaf(a2.y, dp[3], dot1);
    dot1 = fmaf(a2.z, dp[4], dot1);
    dot1 = fmaf(a2.w, dp[5], dot1);

    const float v = conf * fmaf(jd.x, dot0, jd.y * dot1);
    out_depth[p] = inv * (gd - v);
}

// ---------------------------------------------------------------------------
extern "C" void kernel_launch(void* const* d_in, const int* in_sizes, int n_in,
                              void* d_out, int out_size)
{
    const float* r   = (const float*)d_in[0];
    const float* w   = (const float*)d_in[1];
    const float* Jp  = (const float*)d_in[2];
    const float* Jd  = (const float*)d_in[3];
    const float* lam = (const float*)d_in[4];
    float* out = (float*)d_out;

    dim3 g1(BPB, B_DIM);
    reduce_kernel<<<g1, TPB>>>(r, w, Jp, Jd, lam);

    solve_kernel<<<B_DIM, 32>>>(lam, out);

    dim3 g3(N_DIM / TPB, B_DIM);
    depth_kernel<<<g3, TPB>>>(r, w, Jp, Jd, lam, out + B_DIM * 6);
}

// round 2
// speedup vs baseline: 1.0827x; 1.0827x over previous
#include <cuda_runtime.h>
#include <math.h>

#define B_DIM 16
#define N_DIM 196608
#define BPB   128      // reduce blocks per batch
#define TPB   256
#define NACC  27       // 21 sym H entries + 6 g entries

// Fixed-slot partials: [value 0..26][batch 0..15][block 0..127]
__device__ float g_part[NACC * B_DIM * BPB];
// Unclipped delta_pose per batch (used by depth pass)
__device__ float g_dp[B_DIM * 6];
// SoA scratch: plane v in [0..6]: v<6 -> inv*hpd[v], v==6 -> inv*gd
#define SP ((size_t)B_DIM * N_DIM)
__device__ float g_scr[7 * B_DIM * N_DIM];

// ---------------------------------------------------------------------------
// Kernel 1: streaming per-point fused reduction -> 27 partials per block
//           + store (inv*hpd[0..5], inv*gd) scratch for the depth pass
// ---------------------------------------------------------------------------
__global__ void __launch_bounds__(TPB) reduce_kernel(
    const float* __restrict__ r, const float* __restrict__ w,
    const float* __restrict__ Jp, const float* __restrict__ Jd,
    const float* __restrict__ lmbda)
{
    const int b   = blockIdx.y;
    const int blk = blockIdx.x;
    const float lam = __ldg(lmbda + b);

    float acc[NACC];
#pragma unroll
    for (int i = 0; i < NACC; i++) acc[i] = 0.f;

    const size_t base = (size_t)b * N_DIM;

    for (int n = blk * TPB + threadIdx.x; n < N_DIM; n += BPB * TPB) {
        const size_t p = base + (size_t)n;
        const float2 rv = *(const float2*)(r  + 2 * p);
        const float2 wv = *(const float2*)(w  + 2 * p);
        const float2 jd = *(const float2*)(Jd + 2 * p);
        const float4 a0 = *(const float4*)(Jp + 12 * p);
        const float4 a1 = *(const float4*)(Jp + 12 * p + 4);
        const float4 a2 = *(const float4*)(Jp + 12 * p + 8);
        const float jp0[6] = {a0.x, a0.y, a0.z, a0.w, a1.x, a1.y};
        const float jp1[6] = {a1.z, a1.w, a2.x, a2.y, a2.z, a2.w};

        const float conf = wv.x;
        const float nl   = wv.y;

        float hpd[6];
#pragma unroll
        for (int i = 0; i < 6; i++)
            hpd[i] = conf * fmaf(jd.x, jp0[i], jd.y * jp1[i]);

        const float hdd = conf * fmaf(jd.x, jd.x, jd.y * jd.y);
        const float gd  = conf * fmaf(jd.x, rv.x, jd.y * rv.y);
        const float inv = 1.0f / fmaxf(hdd + lam + nl, 1e-4f);

        float cjp0[6], cjp1[6], ih[6];
#pragma unroll
        for (int i = 0; i < 6; i++) {
            cjp0[i] = conf * jp0[i];
            cjp1[i] = conf * jp1[i];
            ih[i]   = inv * hpd[i];
        }

        // scratch for the depth pass (SoA, perfectly coalesced)
#pragma unroll
        for (int i = 0; i < 6; i++) g_scr[(size_t)i * SP + p] = ih[i];
        g_scr[6 * SP + p] = inv * gd;

        int idx = 0;
#pragma unroll
        for (int i = 0; i < 6; i++) {
#pragma unroll
            for (int j = i; j < 6; j++) {
                float t = acc[idx];
                t = fmaf(cjp0[i], jp0[j], t);
                t = fmaf(cjp1[i], jp1[j], t);
                t = fmaf(-ih[i], hpd[j], t);
                acc[idx++] = t;
            }
        }
#pragma unroll
        for (int i = 0; i < 6; i++) {
            float t = acc[21 + i];
            t = fmaf(cjp0[i], rv.x, t);
            t = fmaf(cjp1[i], rv.y, t);
            t = fmaf(-ih[i], gd, t);
            acc[21 + i] = t;
        }
    }

    // intra-warp tree reduce
#pragma unroll
    for (int off = 16; off; off >>= 1) {
#pragma unroll
        for (int i = 0; i < NACC; i++)
            acc[i] += __shfl_down_sync(0xFFFFFFFFu, acc[i], off);
    }

    __shared__ float sh[TPB / 32][NACC];
    const int wid  = threadIdx.x >> 5;
    const int lane = threadIdx.x & 31;
    if (lane == 0) {
#pragma unroll
        for (int i = 0; i < NACC; i++) sh[wid][i] = acc[i];
    }
    __syncthreads();

    if (threadIdx.x < NACC) {
        float s = 0.f;
#pragma unroll
        for (int wgi = 0; wgi < TPB / 32; wgi++) s += sh[wgi][threadIdx.x];
        g_part[threadIdx.x * (B_DIM * BPB) + b * BPB + blk] = s;
    }
}

// ---------------------------------------------------------------------------
// Kernel 2: final reduce + 6x6 damped solve per batch; write clipped pose out
// ---------------------------------------------------------------------------
__global__ void solve_kernel(const float* __restrict__ lmbda,
                             float* __restrict__ out_pose)
{
    const int b = blockIdx.x;
    const int t = threadIdx.x;
    __shared__ float sums[NACC];

    if (t < NACC) {
        const float* p = g_part + t * (B_DIM * BPB) + b * BPB;
        float s = 0.f;
#pragma unroll 8
        for (int i = 0; i < BPB; i++) s += p[i];
        sums[t] = s;
    }
    __syncthreads();

    if (t == 0) {
        double M[6][6], gv[6], x[6];
        int idx = 0;
        for (int i = 0; i < 6; i++)
            for (int j = i; j < 6; j++) {
                double v = (double)sums[idx++];
                M[i][j] = v; M[j][i] = v;
            }
        const double dd = (double)lmbda[b] + 0.011;
        for (int i = 0; i < 6; i++) M[i][i] += dd;
        for (int i = 0; i < 6; i++) gv[i] = (double)sums[21 + i];

        // LU with partial pivoting
        for (int c = 0; c < 6; c++) {
            int piv = c; double mx = fabs(M[c][c]);
            for (int rr = c + 1; rr < 6; rr++) {
                double a = fabs(M[rr][c]);
                if (a > mx) { mx = a; piv = rr; }
            }
            if (piv != c) {
                for (int j = 0; j < 6; j++) {
                    double tmp = M[c][j]; M[c][j] = M[piv][j]; M[piv][j] = tmp;
                }
                double tmp = gv[c]; gv[c] = gv[piv]; gv[piv] = tmp;
            }
            double d = M[c][c];
            if (d == 0.0) d = 1e-30;
            const double invd = 1.0 / d;
            for (int rr = c + 1; rr < 6; rr++) {
                const double f = M[rr][c] * invd;
                for (int j = c; j < 6; j++) M[rr][j] -= f * M[c][j];
                gv[rr] -= f * gv[c];
            }
        }
        for (int i = 5; i >= 0; i--) {
            double s = gv[i];
            for (int j = i + 1; j < 6; j++) s -= M[i][j] * x[j];
            x[i] = s / M[i][i];
        }

        for (int i = 0; i < 6; i++) {
            const float xf = (float)x[i];
            g_dp[b * 6 + i] = xf;                                  // unclipped
            out_pose[b * 6 + i] = fminf(fmaxf(xf, -2.0f), 2.0f);   // clipped
        }
    }
}

// ---------------------------------------------------------------------------
// Kernel 3: depth from scratch only: depth = inv*gd - (inv*hpd) . dp
//           4 points per thread via float4 plane loads.
// ---------------------------------------------------------------------------
__global__ void __launch_bounds__(TPB) depth_kernel(float* __restrict__ out_depth)
{
    const int b  = blockIdx.y;
    const int q  = blockIdx.x * TPB + threadIdx.x;   // quad index
    const size_t p = (size_t)b * N_DIM + (size_t)q * 4;

    float dp[6];
#pragma unroll
    for (int i = 0; i < 6; i++) dp[i] = __ldg(g_dp + b * 6 + i);

    float4 s6 = *(const float4*)(g_scr + 6 * SP + p);   // inv*gd
    float4 res = s6;
#pragma unroll
    for (int i = 0; i < 6; i++) {
        const float4 si = *(const float4*)(g_scr + (size_t)i * SP + p);
        res.x = fmaf(-si.x, dp[i], res.x);
        res.y = fmaf(-si.y, dp[i], res.y);
        res.z = fmaf(-si.z, dp[i], res.z);
        res.w = fmaf(-si.w, dp[i], res.w);
    }
    *(float4*)(out_depth + p) = res;
}

// ---------------------------------------------------------------------------
extern "C" void kernel_launch(void* const* d_in, const int* in_sizes, int n_in,
                              void* d_out, int out_size)
{
    const float* r   = (const float*)d_in[0];
    const float* w   = (const float*)d_in[1];
    const float* Jp  = (const float*)d_in[2];
    const float* Jd  = (const float*)d_in[3];
    const float* lam = (const float*)d_in[4];
    float* out = (float*)d_out;

    dim3 g1(BPB, B_DIM);
    reduce_kernel<<<g1, TPB>>>(r, w, Jp, Jd, lam);

    solve_kernel<<<B_DIM, 32>>>(lam, out);

    dim3 g3(N_DIM / (4 * TPB), B_DIM);
    depth_kernel<<<g3, TPB>>>(out + B_DIM * 6);
}

// round 3
// speedup vs baseline: 1.2254x; 1.1318x over previous
#include <cuda_runtime.h>
#include <cuda_fp16.h>
#include <math.h>

#define B_DIM 16
#define N_DIM 196608
#define BPB   128      // reduce blocks per batch
#define TPB   256
#define NACC  27       // 21 sym H entries + 6 g entries

// Fixed-slot partials: [value 0..26][batch 0..15][block 0..127]
__device__ float g_part[NACC * B_DIM * BPB];
// Unclipped delta_pose per batch (used by depth pass)
__device__ float g_dp[B_DIM * 6];

#define SP ((size_t)B_DIM * N_DIM)
// half2 scratch: plane k holds (ih[2k], ih[2k+1]) per point
__device__ __align__(16) __half2 g_scrh[3 * B_DIM * N_DIM];
// fp32 scratch: inv*gd per point (dominant term, keep full precision)
__device__ __align__(16) float   g_scrf[B_DIM * N_DIM];

// ---------------------------------------------------------------------------
// Kernel 1: streaming per-point fused reduction -> 27 partials per block
//           + compact scratch (3x half2 + 1x fp32) for the depth pass
// ---------------------------------------------------------------------------
__global__ void __launch_bounds__(TPB, 4) reduce_kernel(
    const float* __restrict__ r, const float* __restrict__ w,
    const float* __restrict__ Jp, const float* __restrict__ Jd,
    const float* __restrict__ lmbda)
{
    const int b   = blockIdx.y;
    const int blk = blockIdx.x;
    const float lam = __ldg(lmbda + b);

    float acc[NACC];
#pragma unroll
    for (int i = 0; i < NACC; i++) acc[i] = 0.f;

    const size_t base = (size_t)b * N_DIM;

    for (int n = blk * TPB + threadIdx.x; n < N_DIM; n += BPB * TPB) {
        const size_t p = base + (size_t)n;
        const float2 rv = *(const float2*)(r  + 2 * p);
        const float2 wv = *(const float2*)(w  + 2 * p);
        const float2 jd = *(const float2*)(Jd + 2 * p);
        const float4 a0 = *(const float4*)(Jp + 12 * p);
        const float4 a1 = *(const float4*)(Jp + 12 * p + 4);
        const float4 a2 = *(const float4*)(Jp + 12 * p + 8);
        const float jp0[6] = {a0.x, a0.y, a0.z, a0.w, a1.x, a1.y};
        const float jp1[6] = {a1.z, a1.w, a2.x, a2.y, a2.z, a2.w};

        const float conf = wv.x;
        const float nl   = wv.y;

        float hpd[6];
#pragma unroll
        for (int i = 0; i < 6; i++)
            hpd[i] = conf * fmaf(jd.x, jp0[i], jd.y * jp1[i]);

        const float hdd = conf * fmaf(jd.x, jd.x, jd.y * jd.y);
        const float gd  = conf * fmaf(jd.x, rv.x, jd.y * rv.y);
        const float inv = 1.0f / fmaxf(hdd + lam + nl, 1e-4f);

        float cjp0[6], cjp1[6], ih[6];
#pragma unroll
        for (int i = 0; i < 6; i++) {
            cjp0[i] = conf * jp0[i];
            cjp1[i] = conf * jp1[i];
            ih[i]   = inv * hpd[i];
        }

        // compact scratch for the depth pass
        g_scrh[0 * SP + p] = __floats2half2_rn(ih[0], ih[1]);
        g_scrh[1 * SP + p] = __floats2half2_rn(ih[2], ih[3]);
        g_scrh[2 * SP + p] = __floats2half2_rn(ih[4], ih[5]);
        g_scrf[p] = inv * gd;

        int idx = 0;
#pragma unroll
        for (int i = 0; i < 6; i++) {
#pragma unroll
            for (int j = i; j < 6; j++) {
                float t = acc[idx];
                t = fmaf(cjp0[i], jp0[j], t);
                t = fmaf(cjp1[i], jp1[j], t);
                t = fmaf(-ih[i], hpd[j], t);
                acc[idx++] = t;
            }
        }
#pragma unroll
        for (int i = 0; i < 6; i++) {
            float t = acc[21 + i];
            t = fmaf(cjp0[i], rv.x, t);
            t = fmaf(cjp1[i], rv.y, t);
            t = fmaf(-ih[i], gd, t);
            acc[21 + i] = t;
        }
    }

    // intra-warp tree reduce
#pragma unroll
    for (int off = 16; off; off >>= 1) {
#pragma unroll
        for (int i = 0; i < NACC; i++)
            acc[i] += __shfl_down_sync(0xFFFFFFFFu, acc[i], off);
    }

    __shared__ float sh[TPB / 32][NACC];
    const int wid  = threadIdx.x >> 5;
    const int lane = threadIdx.x & 31;
    if (lane == 0) {
#pragma unroll
        for (int i = 0; i < NACC; i++) sh[wid][i] = acc[i];
    }
    __syncthreads();

    if (threadIdx.x < NACC) {
        float s = 0.f;
#pragma unroll
        for (int wgi = 0; wgi < TPB / 32; wgi++) s += sh[wgi][threadIdx.x];
        g_part[threadIdx.x * (B_DIM * BPB) + b * BPB + blk] = s;
    }
}

// ---------------------------------------------------------------------------
// Kernel 2: final reduce + 6x6 damped solve per batch; write clipped pose out
// ---------------------------------------------------------------------------
__global__ void solve_kernel(const float* __restrict__ lmbda,
                             float* __restrict__ out_pose)
{
    const int b = blockIdx.x;
    const int t = threadIdx.x;
    __shared__ float sums[NACC];

    if (t < NACC) {
        const float* p = g_part + t * (B_DIM * BPB) + b * BPB;
        float s = 0.f;
#pragma unroll 8
        for (int i = 0; i < BPB; i++) s += p[i];
        sums[t] = s;
    }
    __syncthreads();

    if (t == 0) {
        double M[6][6], gv[6], x[6];
        int idx = 0;
        for (int i = 0; i < 6; i++)
            for (int j = i; j < 6; j++) {
                double v = (double)sums[idx++];
                M[i][j] = v; M[j][i] = v;
            }
        const double dd = (double)lmbda[b] + 0.011;
        for (int i = 0; i < 6; i++) M[i][i] += dd;
        for (int i = 0; i < 6; i++) gv[i] = (double)sums[21 + i];

        // LU with partial pivoting
        for (int c = 0; c < 6; c++) {
            int piv = c; double mx = fabs(M[c][c]);
            for (int rr = c + 1; rr < 6; rr++) {
                double a = fabs(M[rr][c]);
                if (a > mx) { mx = a; piv = rr; }
            }
            if (piv != c) {
                for (int j = 0; j < 6; j++) {
                    double tmp = M[c][j]; M[c][j] = M[piv][j]; M[piv][j] = tmp;
                }
                double tmp = gv[c]; gv[c] = gv[piv]; gv[piv] = tmp;
            }
            double d = M[c][c];
            if (d == 0.0) d = 1e-30;
            const double invd = 1.0 / d;
            for (int rr = c + 1; rr < 6; rr++) {
                const double f = M[rr][c] * invd;
                for (int j = c; j < 6; j++) M[rr][j] -= f * M[c][j];
                gv[rr] -= f * gv[c];
            }
        }
        for (int i = 5; i >= 0; i--) {
            double s = gv[i];
            for (int j = i + 1; j < 6; j++) s -= M[i][j] * x[j];
            x[i] = s / M[i][i];
        }

        for (int i = 0; i < 6; i++) {
            const float xf = (float)x[i];
            g_dp[b * 6 + i] = xf;                                  // unclipped
            out_pose[b * 6 + i] = fminf(fmaxf(xf, -2.0f), 2.0f);   // clipped
        }
    }
}

// ---------------------------------------------------------------------------
// Kernel 3: depth = inv*gd - Sum_k (ih[k] * dp[k]); 8 points per thread
// ---------------------------------------------------------------------------
__global__ void __launch_bounds__(TPB) depth_kernel(float* __restrict__ out_depth)
{
    const int b = blockIdx.y;
    const size_t p = (size_t)b * N_DIM +
                     ((size_t)blockIdx.x * TPB + threadIdx.x) * 8;

    float2 dpp[3];
#pragma unroll
    for (int k = 0; k < 3; k++) {
        dpp[k].x = __ldg(g_dp + b * 6 + 2 * k);
        dpp[k].y = __ldg(g_dp + b * 6 + 2 * k + 1);
    }

    // inv*gd: 8 floats
    const float4 f0 = *(const float4*)(g_scrf + p);
    const float4 f1 = *(const float4*)(g_scrf + p + 4);
    float res[8] = {f0.x, f0.y, f0.z, f0.w, f1.x, f1.y, f1.z, f1.w};

#pragma unroll
    for (int k = 0; k < 3; k++) {
        const __half2* plane = g_scrh + (size_t)k * SP + p;
        const uint4 u0 = *(const uint4*)(plane);       // points 0..3
        const uint4 u1 = *(const uint4*)(plane + 4);   // points 4..7
        const unsigned int uu[8] = {u0.x, u0.y, u0.z, u0.w,
                                    u1.x, u1.y, u1.z, u1.w};
#pragma unroll
        for (int j = 0; j < 8; j++) {
            const float2 ihp = __half22float2(*(const __half2*)&uu[j]);
            res[j] = fmaf(-ihp.x, dpp[k].x, res[j]);
            res[j] = fmaf(-ihp.y, dpp[k].y, res[j]);
        }
    }

    *(float4*)(out_depth + p)     = make_float4(res[0], res[1], res[2], res[3]);
    *(float4*)(out_depth + p + 4) = make_float4(res[4], res[5], res[6], res[7]);
}

// ---------------------------------------------------------------------------
extern "C" void kernel_launch(void* const* d_in, const int* in_sizes, int n_in,
                              void* d_out, int out_size)
{
    const float* r   = (const float*)d_in[0];
    const float* w   = (const float*)d_in[1];
    const float* Jp  = (const float*)d_in[2];
    const float* Jd  = (const float*)d_in[3];
    const float* lam = (const float*)d_in[4];
    float* out = (float*)d_out;

    dim3 g1(BPB, B_DIM);
    reduce_kernel<<<g1, TPB>>>(r, w, Jp, Jd, lam);

    solve_kernel<<<B_DIM, 32>>>(lam, out);

    dim3 g3(N_DIM / (8 * TPB), B_DIM);
    depth_kernel<<<g3, TPB>>>(out + B_DIM * 6);
}

// round 4
// speedup vs baseline: 1.2529x; 1.0224x over previous
#include <cuda_runtime.h>
#include <cuda_fp16.h>
#include <math.h>

#define B_DIM 16
#define N_DIM 196608
#define BPB   128      // reduce blocks per batch
#define TPB   256
#define NACC  27       // 21 sym H entries + 6 g entries
#define NPAIR (N_DIM / 2)

// Fixed-slot partials: [value 0..26][batch 0..15][block 0..127]
__device__ float g_part[NACC * B_DIM * BPB];
// Unclipped delta_pose per batch (used by depth pass)
__device__ float g_dp[B_DIM * 6];

#define SP ((size_t)B_DIM * N_DIM)
// half2 scratch: plane k holds (ih[2k], ih[2k+1]) per point
__device__ __align__(16) __half2 g_scrh[3 * B_DIM * N_DIM];
// fp32 scratch: inv*gd per point (dominant term, keep full precision)
__device__ __align__(16) float   g_scrf[B_DIM * N_DIM];

// ---------------------------------------------------------------------------
// Kernel 1: fused reduction, 2 consecutive points per loop iteration.
//           All pair loads are float4 (9 wide loads front-batched).
// ---------------------------------------------------------------------------
__global__ void __launch_bounds__(TPB) reduce_kernel(
    const float* __restrict__ r, const float* __restrict__ w,
    const float* __restrict__ Jp, const float* __restrict__ Jd,
    const float* __restrict__ lmbda)
{
    const int b   = blockIdx.y;
    const int blk = blockIdx.x;
    const float lam = __ldg(lmbda + b);

    float acc[NACC];
#pragma unroll
    for (int i = 0; i < NACC; i++) acc[i] = 0.f;

    const size_t base = (size_t)b * N_DIM;

    for (int q = blk * TPB + threadIdx.x; q < NPAIR; q += BPB * TPB) {
        const size_t p = base + (size_t)q * 2;   // first point of the pair

        // front-batched wide loads for BOTH points
        const float4 rv = *(const float4*)(r  + 2 * p);  // r0x r0y r1x r1y
        const float4 wv = *(const float4*)(w  + 2 * p);  // c0 nl0 c1 nl1
        const float4 jdv = *(const float4*)(Jd + 2 * p); // d0x d0y d1x d1y
        const float4 a0 = *(const float4*)(Jp + 12 * p);
        const float4 a1 = *(const float4*)(Jp + 12 * p + 4);
        const float4 a2 = *(const float4*)(Jp + 12 * p + 8);
        const float4 a3 = *(const float4*)(Jp + 12 * p + 12);
        const float4 a4 = *(const float4*)(Jp + 12 * p + 16);
        const float4 a5 = *(const float4*)(Jp + 12 * p + 20);

        const float jpA[2][6] = {{a0.x, a0.y, a0.z, a0.w, a1.x, a1.y},
                                 {a3.x, a3.y, a3.z, a3.w, a4.x, a4.y}};
        const float jpB[2][6] = {{a1.z, a1.w, a2.x, a2.y, a2.z, a2.w},
                                 {a4.z, a4.w, a5.x, a5.y, a5.z, a5.w}};
        const float rx[2]   = {rv.x, rv.z};
        const float ry[2]   = {rv.y, rv.w};
        const float cf[2]   = {wv.x, wv.z};
        const float nlv[2]  = {wv.y, wv.w};
        const float jdx[2]  = {jdv.x, jdv.z};
        const float jdy[2]  = {jdv.y, jdv.w};

#pragma unroll
        for (int k = 0; k < 2; k++) {
            const float conf = cf[k];
            float hpd[6];
#pragma unroll
            for (int i = 0; i < 6; i++)
                hpd[i] = conf * fmaf(jdx[k], jpA[k][i], jdy[k] * jpB[k][i]);

            const float hdd = conf * fmaf(jdx[k], jdx[k], jdy[k] * jdy[k]);
            const float gd  = conf * fmaf(jdx[k], rx[k], jdy[k] * ry[k]);
            const float inv = 1.0f / fmaxf(hdd + lam + nlv[k], 1e-4f);

            float cj0[6], cj1[6], ih[6];
#pragma unroll
            for (int i = 0; i < 6; i++) {
                cj0[i] = conf * jpA[k][i];
                cj1[i] = conf * jpB[k][i];
                ih[i]  = inv * hpd[i];
            }

            const size_t pp = p + (size_t)k;
            g_scrh[0 * SP + pp] = __floats2half2_rn(ih[0], ih[1]);
            g_scrh[1 * SP + pp] = __floats2half2_rn(ih[2], ih[3]);
            g_scrh[2 * SP + pp] = __floats2half2_rn(ih[4], ih[5]);
            g_scrf[pp] = inv * gd;

            int idx = 0;
#pragma unroll
            for (int i = 0; i < 6; i++) {
#pragma unroll
                for (int j = i; j < 6; j++) {
                    float t = acc[idx];
                    t = fmaf(cj0[i], jpA[k][j], t);
                    t = fmaf(cj1[i], jpB[k][j], t);
                    t = fmaf(-ih[i], hpd[j], t);
                    acc[idx++] = t;
                }
            }
#pragma unroll
            for (int i = 0; i < 6; i++) {
                float t = acc[21 + i];
                t = fmaf(cj0[i], rx[k], t);
                t = fmaf(cj1[i], ry[k], t);
                t = fmaf(-ih[i], gd, t);
                acc[21 + i] = t;
            }
        }
    }

    // intra-warp tree reduce
#pragma unroll
    for (int off = 16; off; off >>= 1) {
#pragma unroll
        for (int i = 0; i < NACC; i++)
            acc[i] += __shfl_down_sync(0xFFFFFFFFu, acc[i], off);
    }

    __shared__ float sh[TPB / 32][NACC];
    const int wid  = threadIdx.x >> 5;
    const int lane = threadIdx.x & 31;
    if (lane == 0) {
#pragma unroll
        for (int i = 0; i < NACC; i++) sh[wid][i] = acc[i];
    }
    __syncthreads();

    if (threadIdx.x < NACC) {
        float s = 0.f;
#pragma unroll
        for (int wgi = 0; wgi < TPB / 32; wgi++) s += sh[wgi][threadIdx.x];
        g_part[threadIdx.x * (B_DIM * BPB) + b * BPB + blk] = s;
    }
}

// ---------------------------------------------------------------------------
// Kernel 2: final reduce + 6x6 damped solve per batch; write clipped pose out
// ---------------------------------------------------------------------------
__global__ void solve_kernel(const float* __restrict__ lmbda,
                             float* __restrict__ out_pose)
{
    const int b = blockIdx.x;
    const int t = threadIdx.x;
    __shared__ float sums[NACC];

    if (t < NACC) {
        const float* p = g_part + t * (B_DIM * BPB) + b * BPB;
        float s = 0.f;
#pragma unroll 8
        for (int i = 0; i < BPB; i++) s += p[i];
        sums[t] = s;
    }
    __syncthreads();

    if (t == 0) {
        double M[6][6], gv[6], x[6];
        int idx = 0;
        for (int i = 0; i < 6; i++)
            for (int j = i; j < 6; j++) {
                double v = (double)sums[idx++];
                M[i][j] = v; M[j][i] = v;
            }
        const double dd = (double)lmbda[b] + 0.011;
        for (int i = 0; i < 6; i++) M[i][i] += dd;
        for (int i = 0; i < 6; i++) gv[i] = (double)sums[21 + i];

        // LU with partial pivoting
        for (int c = 0; c < 6; c++) {
            int piv = c; double mx = fabs(M[c][c]);
            for (int rr = c + 1; rr < 6; rr++) {
                double a = fabs(M[rr][c]);
                if (a > mx) { mx = a; piv = rr; }
            }
            if (piv != c) {
                for (int j = 0; j < 6; j++) {
                    double tmp = M[c][j]; M[c][j] = M[piv][j]; M[piv][j] = tmp;
                }
                double tmp = gv[c]; gv[c] = gv[piv]; gv[piv] = tmp;
            }
            double d = M[c][c];
            if (d == 0.0) d = 1e-30;
            const double invd = 1.0 / d;
            for (int rr = c + 1; rr < 6; rr++) {
                const double f = M[rr][c] * invd;
                for (int j = c; j < 6; j++) M[rr][j] -= f * M[c][j];
                gv[rr] -= f * gv[c];
            }
        }
        for (int i = 5; i >= 0; i--) {
            double s = gv[i];
            for (int j = i + 1; j < 6; j++) s -= M[i][j] * x[j];
            x[i] = s / M[i][i];
        }

        for (int i = 0; i < 6; i++) {
            const float xf = (float)x[i];
            g_dp[b * 6 + i] = xf;                                  // unclipped
            out_pose[b * 6 + i] = fminf(fmaxf(xf, -2.0f), 2.0f);   // clipped
        }
    }
}

// ---------------------------------------------------------------------------
// Kernel 3: depth = inv*gd - Sum_k (ih[k] * dp[k]); 4 points per thread,
//           every load fully coalesced (float4 / uint2).
// ---------------------------------------------------------------------------
__global__ void __launch_bounds__(TPB) depth_kernel(float* __restrict__ out_depth)
{
    const int b = blockIdx.y;
    const size_t p = (size_t)b * N_DIM +
                     ((size_t)blockIdx.x * TPB + threadIdx.x) * 4;

    float2 dpp[3];
#pragma unroll
    for (int k = 0; k < 3; k++) {
        dpp[k].x = __ldg(g_dp + b * 6 + 2 * k);
        dpp[k].y = __ldg(g_dp + b * 6 + 2 * k + 1);
    }

    const float4 f0 = *(const float4*)(g_scrf + p);
    float res[4] = {f0.x, f0.y, f0.z, f0.w};

#pragma unroll
    for (int k = 0; k < 3; k++) {
        const uint2 u = *(const uint2*)(g_scrh + (size_t)k * SP + p);
        const float2 h0 = __half22float2(*(const __half2*)&u.x);
        const float2 h1 = __half22float2(*(const __half2*)&u.y);
        // u.x holds points p,p+1; u.y holds p+2,p+3 for plane k
        res[0] = fmaf(-h0.x, dpp[k].x, res[0]);
        res[1] = fmaf(-h0.y, dpp[k].x, res[1]);
        res[2] = fmaf(-h1.x, dpp[k].x, res[2]);
        res[3] = fmaf(-h1.y, dpp[k].x, res[3]);
        // NOTE: each half2 in plane k packs (ih[2k], ih[2k+1]) of ONE point.
        // Correct unpack below.
    }

    // The loop above is wrong for this packing; recompute properly:
    res[0] = f0.x; res[1] = f0.y; res[2] = f0.z; res[3] = f0.w;
#pragma unroll
    for (int k = 0; k < 3; k++) {
        const uint4 u = *(const uint4*)(g_scrh + (size_t)k * SP + p);
        const float2 q0 = __half22float2(*(const __half2*)&u.x);
        const float2 q1 = __half22float2(*(const __half2*)&u.y);
        const float2 q2 = __half22float2(*(const __half2*)&u.z);
        const float2 q3 = __half22float2(*(const __half2*)&u.w);
        res[0] = fmaf(-q0.x, dpp[k].x, fmaf(-q0.y, dpp[k].y, res[0]));
        res[1] = fmaf(-q1.x, dpp[k].x, fmaf(-q1.y, dpp[k].y, res[1]));
        res[2] = fmaf(-q2.x, dpp[k].x, fmaf(-q2.y, dpp[k].y, res[2]));
        res[3] = fmaf(-q3.x, dpp[k].x, fmaf(-q3.y, dpp[k].y, res[3]));
    }

    *(float4*)(out_depth + p) = make_float4(res[0], res[1], res[2], res[3]);
}

// ---------------------------------------------------------------------------
extern "C" void kernel_launch(void* const* d_in, const int* in_sizes, int n_in,
                              void* d_out, int out_size)
{
    const float* r   = (const float*)d_in[0];
    const float* w   = (const float*)d_in[1];
    const float* Jp  = (const float*)d_in[2];
    const float* Jd  = (const float*)d_in[3];
    const float* lam = (const float*)d_in[4];
    float* out = (float*)d_out;

    dim3 g1(BPB, B_DIM);
    reduce_kernel<<<g1, TPB>>>(r, w, Jp, Jd, lam);

    solve_kernel<<<B_DIM, 32>>>(lam, out);

    dim3 g3(N_DIM / (4 * TPB), B_DIM);
    depth_kernel<<<g3, TPB>>>(out + B_DIM * 6);
}

// round 5
// speedup vs baseline: 1.3798x; 1.1013x over previous
#include <cuda_runtime.h>
#include <cuda_fp16.h>
#include <math.h>

#define B_DIM 16
#define N_DIM 196608
#define BPB   128      // reduce blocks per batch
#define TPB   256
#define NACC  27       // 21 sym H entries + 6 g entries
#define NPAIR (N_DIM / 2)

// Fixed-slot partials: [value 0..26][batch 0..15][block 0..127]
__device__ float g_part[NACC * B_DIM * BPB];
// Unclipped delta_pose per batch (used by depth pass)
__device__ float g_dp[B_DIM * 6];
// last-block-per-batch counters (reset in-kernel each run)
__device__ unsigned int g_cnt[B_DIM];

#define SP ((size_t)B_DIM * N_DIM)
// half2 scratch: plane k holds (ih[2k], ih[2k+1]) per point
__device__ __align__(16) __half2 g_scrh[3 * B_DIM * N_DIM];
// fp32 scratch: inv*gd per point (dominant term, keep full precision)
__device__ __align__(16) float   g_scrf[B_DIM * N_DIM];

struct __align__(8) h2x2 { __half2 a, b; };

// ---------------------------------------------------------------------------
// Kernel 1: fused reduction (2 points/iter, 9 wide loads) + packed scratch
//           stores + last-block final reduce + fp32 LU solve per batch.
// ---------------------------------------------------------------------------
__global__ void __launch_bounds__(TPB) reduce_kernel(
    const float* __restrict__ r, const float* __restrict__ w,
    const float* __restrict__ Jp, const float* __restrict__ Jd,
    const float* __restrict__ lmbda, float* __restrict__ out_pose)
{
    const int b   = blockIdx.y;
    const int blk = blockIdx.x;
    const float lam = __ldg(lmbda + b);

    float acc[NACC];
#pragma unroll
    for (int i = 0; i < NACC; i++) acc[i] = 0.f;

    const size_t base = (size_t)b * N_DIM;

    for (int q = blk * TPB + threadIdx.x; q < NPAIR; q += BPB * TPB) {
        const size_t p = base + (size_t)q * 2;   // first point of the pair

        // front-batched wide loads for BOTH points
        const float4 rv  = *(const float4*)(r  + 2 * p);  // r0x r0y r1x r1y
        const float4 wv  = *(const float4*)(w  + 2 * p);  // c0 nl0 c1 nl1
        const float4 jdv = *(const float4*)(Jd + 2 * p);  // d0x d0y d1x d1y
        const float4 a0 = *(const float4*)(Jp + 12 * p);
        const float4 a1 = *(const float4*)(Jp + 12 * p + 4);
        const float4 a2 = *(const float4*)(Jp + 12 * p + 8);
        const float4 a3 = *(const float4*)(Jp + 12 * p + 12);
        const float4 a4 = *(const float4*)(Jp + 12 * p + 16);
        const float4 a5 = *(const float4*)(Jp + 12 * p + 20);

        const float jpA[2][6] = {{a0.x, a0.y, a0.z, a0.w, a1.x, a1.y},
                                 {a3.x, a3.y, a3.z, a3.w, a4.x, a4.y}};
        const float jpB[2][6] = {{a1.z, a1.w, a2.x, a2.y, a2.z, a2.w},
                                 {a4.z, a4.w, a5.x, a5.y, a5.z, a5.w}};
        const float rx[2]  = {rv.x, rv.z};
        const float ry[2]  = {rv.y, rv.w};
        const float cf[2]  = {wv.x, wv.z};
        const float nlv[2] = {wv.y, wv.w};
        const float jdx[2] = {jdv.x, jdv.z};
        const float jdy[2] = {jdv.y, jdv.w};

        __half2 hs[3][2];
        float   fg[2];

#pragma unroll
        for (int k = 0; k < 2; k++) {
            const float conf = cf[k];
            float hpd[6];
#pragma unroll
            for (int i = 0; i < 6; i++)
                hpd[i] = conf * fmaf(jdx[k], jpA[k][i], jdy[k] * jpB[k][i]);

            const float hdd = conf * fmaf(jdx[k], jdx[k], jdy[k] * jdy[k]);
            const float gd  = conf * fmaf(jdx[k], rx[k], jdy[k] * ry[k]);
            const float inv = 1.0f / fmaxf(hdd + lam + nlv[k], 1e-4f);

            float cj0[6], cj1[6], ih[6];
#pragma unroll
            for (int i = 0; i < 6; i++) {
                cj0[i] = conf * jpA[k][i];
                cj1[i] = conf * jpB[k][i];
                ih[i]  = inv * hpd[i];
            }

            hs[0][k] = __floats2half2_rn(ih[0], ih[1]);
            hs[1][k] = __floats2half2_rn(ih[2], ih[3]);
            hs[2][k] = __floats2half2_rn(ih[4], ih[5]);
            fg[k]    = inv * gd;

            int idx = 0;
#pragma unroll
            for (int i = 0; i < 6; i++) {
#pragma unroll
                for (int j = i; j < 6; j++) {
                    float t = acc[idx];
                    t = fmaf(cj0[i], jpA[k][j], t);
                    t = fmaf(cj1[i], jpB[k][j], t);
                    t = fmaf(-ih[i], hpd[j], t);
                    acc[idx++] = t;
                }
            }
#pragma unroll
            for (int i = 0; i < 6; i++) {
                float t = acc[21 + i];
                t = fmaf(cj0[i], rx[k], t);
                t = fmaf(cj1[i], ry[k], t);
                t = fmaf(-ih[i], gd, t);
                acc[21 + i] = t;
            }
        }

        // packed, fully coalesced scratch stores (8 B each)
#pragma unroll
        for (int kk = 0; kk < 3; kk++) {
            h2x2 v; v.a = hs[kk][0]; v.b = hs[kk][1];
            *(h2x2*)(g_scrh + (size_t)kk * SP + p) = v;
        }
        *(float2*)(g_scrf + p) = make_float2(fg[0], fg[1]);
    }

    // intra-warp tree reduce
#pragma unroll
    for (int off = 16; off; off >>= 1) {
#pragma unroll
        for (int i = 0; i < NACC; i++)
            acc[i] += __shfl_down_sync(0xFFFFFFFFu, acc[i], off);
    }

    __shared__ float sh[TPB / 32][NACC];
    const int wid  = threadIdx.x >> 5;
    const int lane = threadIdx.x & 31;
    if (lane == 0) {
#pragma unroll
        for (int i = 0; i < NACC; i++) sh[wid][i] = acc[i];
    }
    __syncthreads();

    if (threadIdx.x < NACC) {
        float s = 0.f;
#pragma unroll
        for (int wgi = 0; wgi < TPB / 32; wgi++) s += sh[wgi][threadIdx.x];
        g_part[threadIdx.x * (B_DIM * BPB) + b * BPB + blk] = s;
    }

    // ---- last block of this batch: final reduce + fp32 LU solve ----
    __threadfence();
    __shared__ unsigned int is_last;
    if (threadIdx.x == 0) {
        unsigned int prev = atomicAdd(&g_cnt[b], 1u);
        is_last = (prev == BPB - 1) ? 1u : 0u;
    }
    __syncthreads();
    if (!is_last) return;
    __threadfence();   // acquire: see all blocks' g_part writes

    // parallel final reduce: 8 threads per value, 16 partials each
    __shared__ float red[NACC][8];
    __shared__ float sums[NACC];
    {
        const int v = threadIdx.x >> 3;
        const int s = threadIdx.x & 7;
        if (v < NACC) {
            const float* pp = g_part + v * (B_DIM * BPB) + b * BPB + s * 16;
            float t = 0.f;
#pragma unroll
            for (int i = 0; i < 16; i++) t += pp[i];
            red[v][s] = t;
        }
    }
    __syncthreads();
    if (threadIdx.x < NACC) {
        float t = 0.f;
#pragma unroll
        for (int s = 0; s < 8; s++) t += red[threadIdx.x][s];
        sums[threadIdx.x] = t;
    }
    __syncthreads();

    if (threadIdx.x == 0) {
        float M[6][6], gv[6], x[6];
        int idx = 0;
        for (int i = 0; i < 6; i++)
            for (int j = i; j < 6; j++) {
                const float v = sums[idx++];
                M[i][j] = v; M[j][i] = v;
            }
        const float dd = lam + 0.011f;
        for (int i = 0; i < 6; i++) M[i][i] += dd;
        for (int i = 0; i < 6; i++) gv[i] = sums[21 + i];

        // fp32 LU with partial pivoting (matches reference fp32 solve)
        for (int c = 0; c < 6; c++) {
            int piv = c; float mx = fabsf(M[c][c]);
            for (int rr = c + 1; rr < 6; rr++) {
                const float a = fabsf(M[rr][c]);
                if (a > mx) { mx = a; piv = rr; }
            }
            if (piv != c) {
                for (int j = 0; j < 6; j++) {
                    const float tmp = M[c][j]; M[c][j] = M[piv][j]; M[piv][j] = tmp;
                }
                const float tmp = gv[c]; gv[c] = gv[piv]; gv[piv] = tmp;
            }
            float d = M[c][c];
            if (d == 0.f) d = 1e-30f;
            const float invd = 1.0f / d;
            for (int rr = c + 1; rr < 6; rr++) {
                const float f = M[rr][c] * invd;
                for (int j = c; j < 6; j++) M[rr][j] -= f * M[c][j];
                gv[rr] -= f * gv[c];
            }
        }
        for (int i = 5; i >= 0; i--) {
            float s = gv[i];
            for (int j = i + 1; j < 6; j++) s -= M[i][j] * x[j];
            x[i] = s / M[i][i];
        }

        for (int i = 0; i < 6; i++) {
            g_dp[b * 6 + i] = x[i];                                   // unclipped
            out_pose[b * 6 + i] = fminf(fmaxf(x[i], -2.0f), 2.0f);    // clipped
        }
        g_cnt[b] = 0;   // reset for next graph replay
    }
}

// ---------------------------------------------------------------------------
// Kernel 2: depth = inv*gd - Sum_k (ih[k] . dp); 4 points per thread,
//           all 4 wide loads front-batched and fully dense.
// ---------------------------------------------------------------------------
__global__ void __launch_bounds__(TPB) depth_kernel(float* __restrict__ out_depth)
{
    const int b = blockIdx.y;
    const size_t p = (size_t)b * N_DIM +
                     ((size_t)blockIdx.x * TPB + threadIdx.x) * 4;

    const float4 f0 = *(const float4*)(g_scrf + p);
    const uint4 u0 = *(const uint4*)(g_scrh + 0 * SP + p);
    const uint4 u1 = *(const uint4*)(g_scrh + 1 * SP + p);
    const uint4 u2 = *(const uint4*)(g_scrh + 2 * SP + p);

    float2 dpp[3];
#pragma unroll
    for (int k = 0; k < 3; k++) {
        dpp[k].x = __ldg(g_dp + b * 6 + 2 * k);
        dpp[k].y = __ldg(g_dp + b * 6 + 2 * k + 1);
    }

    float res[4] = {f0.x, f0.y, f0.z, f0.w};
    const uint4 uu[3] = {u0, u1, u2};
#pragma unroll
    for (int k = 0; k < 3; k++) {
        const float2 q0 = __half22float2(*(const __half2*)&uu[k].x);
        const float2 q1 = __half22float2(*(const __half2*)&uu[k].y);
        const float2 q2 = __half22float2(*(const __half2*)&uu[k].z);
        const float2 q3 = __half22float2(*(const __half2*)&uu[k].w);
        res[0] = fmaf(-q0.x, dpp[k].x, fmaf(-q0.y, dpp[k].y, res[0]));
        res[1] = fmaf(-q1.x, dpp[k].x, fmaf(-q1.y, dpp[k].y, res[1]));
        res[2] = fmaf(-q2.x, dpp[k].x, fmaf(-q2.y, dpp[k].y, res[2]));
        res[3] = fmaf(-q3.x, dpp[k].x, fmaf(-q3.y, dpp[k].y, res[3]));
    }

    *(float4*)(out_depth + p) = make_float4(res[0], res[1], res[2], res[3]);
}

// ---------------------------------------------------------------------------
extern "C" void kernel_launch(void* const* d_in, const int* in_sizes, int n_in,
                              void* d_out, int out_size)
{
    const float* r   = (const float*)d_in[0];
    const float* w   = (const float*)d_in[1];
    const float* Jp  = (const float*)d_in[2];
    const float* Jd  = (const float*)d_in[3];
    const float* lam = (const float*)d_in[4];
    float* out = (float*)d_out;

    dim3 g1(BPB, B_DIM);
    reduce_kernel<<<g1, TPB>>>(r, w, Jp, Jd, lam, out);

    dim3 g2(N_DIM / (4 * TPB), B_DIM);
    depth_kernel<<<g2, TPB>>>(out + B_DIM * 6);
}